// round 4
// baseline (speedup 1.0000x reference)
#include <cuda_runtime.h>

typedef unsigned long long u64;

#define NITER 31
#define RPT 4
#define BLOCK 256

__device__ double   g_sum   = 0.0;
__device__ unsigned g_count = 0;

__device__ __forceinline__ u64 pk2(float a, float b) {
    u64 r; asm("mov.b64 %0, {%1, %2};" : "=l"(r) : "f"(a), "f"(b)); return r;
}
__device__ __forceinline__ void up2(u64 v, float &a, float &b) {
    asm("mov.b64 {%0, %1}, %2;" : "=f"(a), "=f"(b) : "l"(v));
}
__device__ __forceinline__ u64 ffma2(u64 a, u64 b, u64 c) {
    u64 d; asm("fma.rn.f32x2 %0, %1, %2, %3;" : "=l"(d) : "l"(a), "l"(b), "l"(c)); return d;
}
__device__ __forceinline__ u64 fmul2(u64 a, u64 b) {
    u64 d; asm("mul.rn.f32x2 %0, %1, %2;" : "=l"(d) : "l"(a), "l"(b)); return d;
}
__device__ __forceinline__ u64 fsub2(u64 a, u64 b) {
    u64 d; asm("sub.rn.f32x2 %0, %1, %2;" : "=l"(d) : "l"(a), "l"(b)); return d;
}
__device__ __forceinline__ float frcp_(float x) {
    float r; asm("rcp.approx.f32 %0, %1;" : "=f"(r) : "f"(x)); return r;
}

__global__ void __launch_bounds__(BLOCK, 6)
lm_kernel(const float* __restrict__ P, const float* __restrict__ V,
          const float* __restrict__ R, const float* __restrict__ T,
          const float* __restrict__ Cs, const float* __restrict__ loss_in,
          float* __restrict__ out, int n, double invN)
{
    const int g = blockIdx.x * BLOCK + threadIdx.x;
    const int base = g * RPT;

    float ssum = 0.0f;

    if (base < n) {
        const float r00 = __ldg(R + 0), r01 = __ldg(R + 1), r02 = __ldg(R + 2);
        const float r10 = __ldg(R + 3), r11 = __ldg(R + 4), r12 = __ldg(R + 5);
        const float r20 = __ldg(R + 6), r21 = __ldg(R + 7), r22 = __ldg(R + 8);
        const float tx = __ldg(T + 0), ty = __ldg(T + 1), tz = __ldg(T + 2);
        const float c   = __ldg(Cs);
        const float mc  = -c;
        const float m2c = -2.0f * c;

        float px[RPT], py[RPT], pz[RPT], wx[RPT], wy[RPT], wz[RPT];
        if (base + RPT <= n) {
            const float4* P4 = (const float4*)P;
            const float4* V4 = (const float4*)V;
            float4 a0 = P4[3*g + 0], a1 = P4[3*g + 1], a2 = P4[3*g + 2];
            float4 b0 = V4[3*g + 0], b1 = V4[3*g + 1], b2 = V4[3*g + 2];
            px[0]=a0.x; py[0]=a0.y; pz[0]=a0.z;
            px[1]=a0.w; py[1]=a1.x; pz[1]=a1.y;
            px[2]=a1.z; py[2]=a1.w; pz[2]=a2.x;
            px[3]=a2.y; py[3]=a2.z; pz[3]=a2.w;
            wx[0]=b0.x; wy[0]=b0.y; wz[0]=b0.z;
            wx[1]=b0.w; wy[1]=b1.x; wz[1]=b1.y;
            wx[2]=b1.z; wy[2]=b1.w; wz[2]=b2.x;
            wx[3]=b2.y; wy[3]=b2.z; wz[3]=b2.w;
        } else {
            #pragma unroll
            for (int k = 0; k < RPT; ++k) {
                int i = base + k;
                if (i < n) {
                    px[k]=P[3*i]; py[k]=P[3*i+1]; pz[k]=P[3*i+2];
                    wx[k]=V[3*i]; wy[k]=V[3*i+1]; wz[k]=V[3*i+2];
                } else {
                    // dummy ray, remapped below to A=1,B=1,C=0 (F ends at 0)
                    px[k]=0.f; py[k]=0.f; pz[k]=0.f;
                    wx[k]=1.f; wy[k]=0.f; wz[k]=0.f;
                }
            }
        }

        // Per ray: transform to local frame, reduce f(t)=A t^2 + B t + C,
        // substitute s = 2At + B:  s' = s - s(s^2-D)/(2 s^2 + 1),
        // D = B^2 - 4AC, final F = (s^2 - D)/(4A).
        float Dk[RPT], Sk[RPT], I4[RPT];
        #pragma unroll
        for (int k = 0; k < RPT; ++k) {
            float qx = px[k] - tx, qy = py[k] - ty, qz = pz[k] - tz;
            float plx = qx*r00 + qy*r10 + qz*r20;
            float ply = qx*r01 + qy*r11 + qz*r21;
            float plz = qx*r02 + qy*r12 + qz*r22;
            float vlx = wx[k]*r00 + wy[k]*r10 + wz[k]*r20;
            float vly = wx[k]*r01 + wy[k]*r11 + wz[k]*r21;
            float vlz = wx[k]*r02 + wy[k]*r12 + wz[k]*r22;
            float A = mc * (vly*vly + vlz*vlz);
            float B = fmaf(m2c, ply*vly + plz*vlz, vlx);
            float C = fmaf(mc,  ply*ply + plz*plz, plx);
            if (A == 0.0f) { A = 1.0f; B = 1.0f; C = 0.0f; }
            float AC = A * C;
            Dk[k] = fmaf(AC, -4.0f, B * B);   // D = B^2 - 4AC
            Sk[k] = B;                        // s0 = B
            I4[k] = frcp_(4.0f * A);          // 1/(4A) for the epilogue
        }

        const u64 TWO2 = 0x4000000040000000ULL;  // (2, 2)
        const u64 ONE2 = 0x3F8000003F800000ULL;  // (1, 1)

        const u64 D0 = pk2(Dk[0], Dk[1]), D1 = pk2(Dk[2], Dk[3]);
        const u64 I40 = pk2(I4[0], I4[1]), I41 = pk2(I4[2], I4[3]);
        u64 s0 = pk2(Sk[0], Sk[1]),        s1 = pk2(Sk[2], Sk[3]);

        #pragma unroll
        for (int it = 0; it < NITER; ++it) {
            u64 q0 = fmul2(s0, s0);
            u64 q1 = fmul2(s1, s1);
            u64 w0 = fsub2(D0, q0);          // D - s^2 (negated numerator)
            u64 w1 = fsub2(D1, q1);
            u64 d0 = ffma2(q0, TWO2, ONE2);  // 2 s^2 + 1  (>= 1 always)
            u64 d1 = ffma2(q1, TWO2, ONE2);
            u64 n0 = fmul2(s0, w0);          // -s (s^2 - D)
            u64 n1 = fmul2(s1, w1);
            u64 m  = fmul2(d0, d1);          // lane-wise product of both dens
            float ma, mb; up2(m, ma, mb);
            u64 rp = pk2(frcp_(ma), frcp_(mb));
            u64 r0 = fmul2(rp, d1);          // 1/d0 per lane
            u64 r1 = fmul2(rp, d0);          // 1/d1 per lane
            s0 = ffma2(n0, r0, s0);          // s - s(s^2-D)/(2s^2+1)
            s1 = ffma2(n1, r1, s1);
        }

        // F = (s^2 - D)/(4A); accumulate F^2 (sign-free)
        u64 q0 = fmul2(s0, s0);
        u64 q1 = fmul2(s1, s1);
        u64 w0 = fsub2(D0, q0);
        u64 w1 = fsub2(D1, q1);
        u64 F0 = fmul2(w0, I40);             // -F
        u64 F1 = fmul2(w1, I41);
        u64 ss = fmul2(F0, F0);
        ss = ffma2(F1, F1, ss);
        float sa, sb; up2(ss, sa, sb);
        ssum = sa + sb;
    }

    // Block tree reduction (float)
    #pragma unroll
    for (int o = 16; o > 0; o >>= 1)
        ssum += __shfl_xor_sync(0xffffffffu, ssum, o);
    __shared__ float wsum[BLOCK / 32];
    if ((threadIdx.x & 31) == 0) wsum[threadIdx.x >> 5] = ssum;
    __syncthreads();

    // Global double accumulation + last-block finalize (self-resetting for
    // identical behavior on every graph replay).
    if (threadIdx.x == 0) {
        float bsum = 0.0f;
        #pragma unroll
        for (int w = 0; w < BLOCK / 32; ++w) bsum += wsum[w];
        atomicAdd(&g_sum, (double)bsum);
        __threadfence();
        unsigned old = atomicAdd(&g_count, 1u);
        if (old == gridDim.x - 1) {
            __threadfence();
            double tot = g_sum;
            out[0] = (float)((double)loss_in[0] + tot * invN);
            g_sum = 0.0;
            __threadfence();
            g_count = 0;
        }
    }
}

extern "C" void kernel_launch(void* const* d_in, const int* in_sizes, int n_in,
                              void* d_out, int out_size)
{
    const float* P       = (const float*)d_in[0];
    const float* V       = (const float*)d_in[1];
    const float* R       = (const float*)d_in[2];
    const float* T       = (const float*)d_in[3];
    const float* c       = (const float*)d_in[4];
    const float* loss_in = (const float*)d_in[5];

    const int n = in_sizes[0] / 3;                 // number of rays
    int nthreads = (n + RPT - 1) / RPT;
    int nblocks  = (nthreads + BLOCK - 1) / BLOCK; // 4096 for N=4.19M

    lm_kernel<<<nblocks, BLOCK>>>(P, V, R, T, c, loss_in,
                                  (float*)d_out, n, 1.0 / (double)n);
}